// round 1
// baseline (speedup 1.0000x reference)
#include <cuda_runtime.h>
#include <math.h>

#define SUB   20
#define TNO   201
#define ENO   2000
#define INO   500
#define TD    20000
#define KTOT  2500
#define NQ    4        // K-split of the e-GEMM

// ---------------- device scratch (no allocs allowed) ----------------
__device__ float g_Ct[KTOT * 64];          // [k][c] c: 0..19 hard, 20..39 soft, 40..59 softzb, 60..63 pad
__device__ float g_inE[NQ][TD * 64];       // partial e-GEMM results
__device__ float g_inI[TD * 64];
__device__ float g_syn[60][TD];            // FIR output, channel-major

// ---------------- kernel 1: prep (theta, z's, C matrices) ----------------
__global__ void prep_kernel(const float* __restrict__ u, const float* __restrict__ v,
                            const float* __restrict__ cl, float* __restrict__ out) {
    int n = blockIdx.x * blockDim.x + threadIdx.x;
    if (n >= KTOT) return;
    float c[SUB], theta[SUB], rz[SUB];
    float m = -1e30f;
#pragma unroll
    for (int s = 0; s < SUB; s++) { c[s] = cl[s * KTOT + n]; m = fmaxf(m, c[s]); }
    float sum = 0.f;
#pragma unroll
    for (int s = 0; s < SUB; s++) { theta[s] = expf(c[s] - m); sum += theta[s]; }
    float inv = 1.0f / sum;
    int k = 0; float best = -1e30f;
#pragma unroll
    for (int s = 0; s < SUB; s++) {
        theta[s] *= inv;
        float uu = u[s * KTOT + n];
        rz[s] = logf(theta[s]) - logf(-logf(uu));
        if (rz[s] > best) { best = rz[s]; k = s; }
    }
    float vk = v[k * KTOT + n];
    float lvk = logf(vk);
#pragma unroll
    for (int s = 0; s < SUB; s++) {
        float hard = (s == k) ? 1.0f : 0.0f;
        float soft = 1.0f / (1.0f + expf(-2.0f * rz[s])) + 1e-9f;
        float vv = v[s * KTOT + n];
        float zb = (s == k) ? -logf(-logf(vv))
                            : -logf((-logf(vv)) / theta[s] - lvk);
        float szb = 1.0f / (1.0f + expf(-2.0f * zb)) + 1e-9f;
        out[ 60000 + s * KTOT + n] = theta[s];
        out[110000 + s * KTOT + n] = hard;
        out[160000 + s * KTOT + n] = soft;
        out[210000 + s * KTOT + n] = szb;
        g_Ct[n * 64 + s]      = hard;
        g_Ct[n * 64 + 20 + s] = soft;
        g_Ct[n * 64 + 40 + s] = szb;
    }
#pragma unroll
    for (int p = 60; p < 64; p++) g_Ct[n * 64 + p] = 0.0f;
}

// ---------------- kernel 2: GEMM (20000 x 500-chunk) @ (500 x 64) ----------------
#define BM 128
#define BK 20
#define BN 64

__global__ __launch_bounds__(128) void gemm_kernel(const float* __restrict__ Se,
                                                   const float* __restrict__ Si) {
    __shared__ __align__(16) float As[BK][BM + 4];
    __shared__ __align__(16) float Bs[BK][BN];
    int q  = blockIdx.y;                 // 0..3 = e quarters, 4 = i
    int t0 = blockIdx.x * BM;
    const float* A; int lda, k0base, ctbase; float* outp;
    if (q < NQ) { A = Se; lda = ENO; k0base = q * 500; ctbase = q * 500; outp = g_inE[q]; }
    else        { A = Si; lda = INO; k0base = 0;       ctbase = 2000;    outp = g_inI;    }
    int tid = threadIdx.x;
    int m0 = (tid >> 3) * 8;
    int n0 = (tid & 7) * 8;
    float acc[8][8];
#pragma unroll
    for (int i = 0; i < 8; i++)
#pragma unroll
        for (int j = 0; j < 8; j++) acc[i][j] = 0.f;

    for (int kc = 0; kc < 500; kc += BK) {
        // A tile: 128 rows x 20 cols = 640 float4
#pragma unroll
        for (int r = 0; r < 5; r++) {
            int fi = tid + 128 * r;
            int row = fi / 5, c4 = fi % 5;
            int t = t0 + row;
            float4 val = make_float4(0.f, 0.f, 0.f, 0.f);
            if (t < TD)
                val = *(const float4*)&A[(size_t)t * lda + k0base + kc + c4 * 4];
            As[c4 * 4 + 0][row] = val.x;
            As[c4 * 4 + 1][row] = val.y;
            As[c4 * 4 + 2][row] = val.z;
            As[c4 * 4 + 3][row] = val.w;
        }
        // B tile: 20 x 64 = 320 float4
#pragma unroll
        for (int r = 0; r < 3; r++) {
            int fi = tid + 128 * r;
            if (fi < 320) {
                int row = fi / 16, c4 = fi % 16;
                *(float4*)&Bs[row][c4 * 4] =
                    *(const float4*)&g_Ct[(ctbase + kc + row) * 64 + c4 * 4];
            }
        }
        __syncthreads();
#pragma unroll
        for (int kk = 0; kk < BK; kk++) {
            float a[8], b[8];
            *(float4*)&a[0] = *(float4*)&As[kk][m0];
            *(float4*)&a[4] = *(float4*)&As[kk][m0 + 4];
            *(float4*)&b[0] = *(float4*)&Bs[kk][n0];
            *(float4*)&b[4] = *(float4*)&Bs[kk][n0 + 4];
#pragma unroll
            for (int i = 0; i < 8; i++)
#pragma unroll
                for (int j = 0; j < 8; j++) acc[i][j] += a[i] * b[j];
        }
        __syncthreads();
    }
#pragma unroll
    for (int i = 0; i < 8; i++) {
        int t = t0 + m0 + i;
        if (t < TD) {
            *(float4*)&outp[t * 64 + n0]     = make_float4(acc[i][0], acc[i][1], acc[i][2], acc[i][3]);
            *(float4*)&outp[t * 64 + n0 + 4] = make_float4(acc[i][4], acc[i][5], acc[i][6], acc[i][7]);
        }
    }
}

// ---------------- kernel 3: 201-tap causal FIR per channel ----------------
#define TT 1024

__global__ __launch_bounds__(256) void fir_kernel(const float* __restrict__ Wsyn,
                                                  const float* __restrict__ Tausyn,
                                                  const float* __restrict__ Dsyn) {
    __shared__ __align__(16) float xe[1232];   // 4 front-pad + 1224 + tail pad
    __shared__ __align__(16) float xi[1232];
    __shared__ __align__(16) float ke[204];
    __shared__ __align__(16) float ki[204];
    int p  = blockIdx.y;          // channel 0..59 (= var*20 + s, matches g_in column)
    int s  = p % 20;
    int c  = p;
    int t0 = blockIdx.x * TT;
    int tid = threadIdx.x;

    if (tid < 204) {
        if (tid < 201) {
            float itau0 = expf(-Tausyn[s * 2 + 0]);
            float itau1 = expf(-Tausyn[s * 2 + 1]);
            float d0 = expf(Dsyn[s * 2 + 0]);
            float d1 = expf(Dsyn[s * 2 + 1]);
            float w0 = Wsyn[s * 2 + 0], w1 = Wsyn[s * 2 + 1];
            float t = fmaxf((float)tid - d0, 0.0f);
            float tt_ = t * itau0;
            ke[tid] = tt_ * expf(-tt_) * w0;
            t = fmaxf((float)tid - d1, 0.0f);
            tt_ = t * itau1;
            ki[tid] = tt_ * expf(-tt_) * w1;
        } else { ke[tid] = 0.f; ki[tid] = 0.f; }
    }
    for (int idx = tid; idx < TT + 200; idx += 256) {
        int g = t0 - 200 + idx;
        float ve = 0.f, vi = 0.f;
        if (g >= 0 && g < TD) {
            ve = g_inE[0][g * 64 + c] + g_inE[1][g * 64 + c]
               + g_inE[2][g * 64 + c] + g_inE[3][g * 64 + c];
            vi = g_inI[g * 64 + c];
        }
        xe[4 + idx] = ve;
        xi[4 + idx] = vi;
    }
    if (tid < 4) { xe[tid] = 0.f; xi[tid] = 0.f; }
    __syncthreads();

    float acc0 = 0.f, acc1 = 0.f, acc2 = 0.f, acc3 = 0.f;
    int pos = 200 + tid * 4;
    {
        float w[8];
        *(float4*)&w[4] = *(float4*)&xe[4 + pos];
#pragma unroll 4
        for (int tau = 0; tau <= 200; tau += 4) {
            *(float4*)&w[0] = *(float4*)&xe[pos - tau];   // logical pos-tau-4 (+4 base shift)
            float4 kk = *(float4*)&ke[tau];
            acc0 += kk.x * w[4]; acc1 += kk.x * w[5]; acc2 += kk.x * w[6]; acc3 += kk.x * w[7];
            acc0 += kk.y * w[3]; acc1 += kk.y * w[4]; acc2 += kk.y * w[5]; acc3 += kk.y * w[6];
            acc0 += kk.z * w[2]; acc1 += kk.z * w[3]; acc2 += kk.z * w[4]; acc3 += kk.z * w[5];
            acc0 += kk.w * w[1]; acc1 += kk.w * w[2]; acc2 += kk.w * w[3]; acc3 += kk.w * w[4];
            w[4] = w[0]; w[5] = w[1]; w[6] = w[2]; w[7] = w[3];
        }
    }
    {
        float w[8];
        *(float4*)&w[4] = *(float4*)&xi[4 + pos];
#pragma unroll 4
        for (int tau = 0; tau <= 200; tau += 4) {
            *(float4*)&w[0] = *(float4*)&xi[pos - tau];
            float4 kk = *(float4*)&ki[tau];
            acc0 += kk.x * w[4]; acc1 += kk.x * w[5]; acc2 += kk.x * w[6]; acc3 += kk.x * w[7];
            acc0 += kk.y * w[3]; acc1 += kk.y * w[4]; acc2 += kk.y * w[5]; acc3 += kk.y * w[6];
            acc0 += kk.z * w[2]; acc1 += kk.z * w[3]; acc2 += kk.z * w[4]; acc3 += kk.z * w[5];
            acc0 += kk.w * w[1]; acc1 += kk.w * w[2]; acc2 += kk.w * w[3]; acc3 += kk.w * w[4];
            w[4] = w[0]; w[5] = w[1]; w[6] = w[2]; w[7] = w[3];
        }
    }
    int t = t0 + tid * 4;
    if (t < TD)
        *(float4*)&g_syn[p][t] = make_float4(acc0, acc1, acc2, acc3);
}

// ---------------- kernel 4: subunit tree + output ----------------
__global__ void tree_kernel(const float* __restrict__ Wsub, const float* __restrict__ Vo,
                            float* __restrict__ out) {
    int t = blockIdx.x * blockDim.x + threadIdx.x;
    if (t >= TD) return;
    float W[20];
#pragma unroll
    for (int s = 0; s < 20; s++) W[s] = Wsub[s];
    float vo = Vo[0];
#pragma unroll
    for (int var = 0; var < 3; var++) {
        float sub[20];
#pragma unroll
        for (int s = 19; s >= 10; s--) sub[s] = tanhf(g_syn[var * 20 + s][t]);
        sub[9] = tanhf(g_syn[var * 20 + 9][t] + sub[19] * W[19]);
#pragma unroll
        for (int s = 8; s >= 0; s--)
            sub[s] = tanhf(g_syn[var * 20 + s][t]
                           + sub[2 * s + 1] * W[2 * s + 1]
                           + sub[2 * s + 2] * W[2 * s + 2]);
        out[var * TD + t] = sub[0] * W[0] + vo;
    }
}

// ---------------- launch ----------------
extern "C" void kernel_launch(void* const* d_in, const int* in_sizes, int n_in,
                              void* d_out, int out_size) {
    const float* Se   = (const float*)d_in[0];
    const float* Si   = (const float*)d_in[1];
    const float* u    = (const float*)d_in[2];
    const float* v    = (const float*)d_in[3];
    const float* Wsyn = (const float*)d_in[4];
    const float* Tau  = (const float*)d_in[5];
    const float* Dlt  = (const float*)d_in[6];
    const float* Wsub = (const float*)d_in[7];
    const float* Vo   = (const float*)d_in[8];
    // d_in[9] = Theta (unused by reference)
    const float* Cl   = (const float*)d_in[10];
    float* out = (float*)d_out;

    prep_kernel<<<(KTOT + 255) / 256, 256>>>(u, v, Cl, out);
    dim3 gg((TD + BM - 1) / BM, NQ + 1);       // (157, 5)
    gemm_kernel<<<gg, 128>>>(Se, Si);
    dim3 gf((TD + TT - 1) / TT, 60);           // (20, 60)
    fir_kernel<<<gf, 256>>>(Wsyn, Tau, Dlt);
    tree_kernel<<<(TD + 255) / 256, 256>>>(Wsub, Vo, out);
}

// round 3
// speedup vs baseline: 1.6608x; 1.6608x over previous
#include <cuda_runtime.h>
#include <math.h>

#define SUB   20
#define ENO   2000
#define INO   500
#define TD    20000
#define KTOT  2500
#define NQ    4
#define NTAPS 72

// ---------------- device scratch ----------------
__device__ float g_Ct[KTOT * 64];          // [k][c]: 0..19 hard, 20..39 soft, 40..59 softzb, 60..63 pad (tf32-rounded)
__device__ float g_inE[NQ][TD * 64];       // partial e-GEMM results
__device__ float g_inI[TD * 64];
__device__ float g_syn[60][TD];

__device__ __forceinline__ float to_tf32(float x) {
    asm("cvt.rna.tf32.f32 %0, %1;" : "=f"(x) : "f"(x));
    return x;
}

// ---------------- kernel 1: prep (warp per column n, s -> lane) ----------------
__global__ __launch_bounds__(128) void prep_kernel(const float* __restrict__ u,
                                                   const float* __restrict__ v,
                                                   const float* __restrict__ cl,
                                                   float* __restrict__ out) {
    int warp = threadIdx.x >> 5, lane = threadIdx.x & 31;
    int n = blockIdx.x * 4 + warp;
    if (n >= KTOT) return;
    int s = lane;
    bool act = (s < SUB);

    float c = act ? cl[s * KTOT + n] : -1e30f;
    float m = c;
#pragma unroll
    for (int o = 16; o; o >>= 1) m = fmaxf(m, __shfl_xor_sync(0xffffffffu, m, o));
    float e = act ? expf(c - m) : 0.0f;
    float sum = e;
#pragma unroll
    for (int o = 16; o; o >>= 1) sum += __shfl_xor_sync(0xffffffffu, sum, o);
    float theta = e / sum;

    float uu = act ? u[s * KTOT + n] : 0.5f;
    float vv = act ? v[s * KTOT + n] : 0.5f;
    float rz = act ? (logf(theta) - logf(-logf(uu))) : -1e30f;

    // argmax with first-index tie break
    float best = rz; int bidx = s;
#pragma unroll
    for (int o = 16; o; o >>= 1) {
        float ob = __shfl_xor_sync(0xffffffffu, best, o);
        int   oi = __shfl_xor_sync(0xffffffffu, bidx, o);
        if (ob > best || (ob == best && oi < bidx)) { best = ob; bidx = oi; }
    }
    int k = bidx;
    float vk  = __shfl_sync(0xffffffffu, vv, k);
    float lvk = logf(vk);

    if (act) {
        float hard = (s == k) ? 1.0f : 0.0f;
        float soft = 1.0f / (1.0f + expf(-2.0f * rz)) + 1e-9f;
        float zb   = (s == k) ? -logf(-logf(vv))
                              : -logf((-logf(vv)) / theta - lvk);
        float szb  = 1.0f / (1.0f + expf(-2.0f * zb)) + 1e-9f;
        out[ 60000 + s * KTOT + n] = theta;
        out[110000 + s * KTOT + n] = hard;
        out[160000 + s * KTOT + n] = soft;
        out[210000 + s * KTOT + n] = szb;
        g_Ct[n * 64 + s]      = hard;                // exact in tf32
        g_Ct[n * 64 + 20 + s] = to_tf32(soft);
        g_Ct[n * 64 + 40 + s] = to_tf32(szb);
    } else if (s < 24) {
        g_Ct[n * 64 + 40 + s] = 0.0f;                // pad cols 60..63
    }
}

// ---------------- kernel 2: tf32 tensor-core GEMM ----------------
// per block: 128 rows x 64 cols x K=500 chunk. 4 warps, each 32 rows.
#define BM 128

__global__ __launch_bounds__(128) void gemm_kernel(const float* __restrict__ Se,
                                                   const float* __restrict__ Si) {
    __shared__ __align__(16) float As[BM][44];   // rows 0..31 of K used; pad 44 -> conflict-free
    __shared__ __align__(16) float Bs[32][72];
    int q  = blockIdx.y;
    int t0 = blockIdx.x * BM;
    const float* A; int lda, k0, ctb; float* outp;
    if (q < NQ) { A = Se; lda = ENO; k0 = q * 500; ctb = q * 500; outp = g_inE[q]; }
    else        { A = Si; lda = INO; k0 = 0;       ctb = 2000;    outp = g_inI;    }

    int tid = threadIdx.x, warp = tid >> 5, lane = tid & 31;
    int qd = lane >> 2, r = lane & 3;
    int mW = warp * 32;

    float acc[2][8][4];
#pragma unroll
    for (int a = 0; a < 2; a++)
#pragma unroll
        for (int b = 0; b < 8; b++)
#pragma unroll
            for (int c = 0; c < 4; c++) acc[a][b][c] = 0.0f;

    int t = t0 + tid;
    bool trow = (t < TD);

    for (int kc = 0; kc < 16; kc++) {
        // stage A: each thread loads its row, 32 k-cols (tf32-rounded)
#pragma unroll
        for (int c4 = 0; c4 < 8; c4++) {
            int klocal = kc * 32 + c4 * 4;
            float4 val = make_float4(0.f, 0.f, 0.f, 0.f);
            if (trow && klocal < 500)
                val = *(const float4*)&A[(size_t)t * lda + k0 + klocal];
            val.x = to_tf32(val.x); val.y = to_tf32(val.y);
            val.z = to_tf32(val.z); val.w = to_tf32(val.w);
            *(float4*)&As[tid][c4 * 4] = val;
        }
        // stage B: 32 x 64 floats
#pragma unroll
        for (int rr = 0; rr < 4; rr++) {
            int fi = tid + 128 * rr;
            int row = fi >> 4, c4 = fi & 15;
            int klocal = kc * 32 + row;
            float4 val = make_float4(0.f, 0.f, 0.f, 0.f);
            if (klocal < 500)
                val = *(const float4*)&g_Ct[(ctb + klocal) * 64 + c4 * 4];
            *(float4*)&Bs[row][c4 * 4] = val;
        }
        __syncthreads();

#pragma unroll
        for (int kk = 0; kk < 32; kk += 8) {
            unsigned a[2][4], b[8][2];
#pragma unroll
            for (int tM = 0; tM < 2; tM++) {
                int mb = mW + tM * 16 + qd;
                a[tM][0] = __float_as_uint(As[mb    ][kk + r    ]);
                a[tM][1] = __float_as_uint(As[mb + 8][kk + r    ]);
                a[tM][2] = __float_as_uint(As[mb    ][kk + r + 4]);
                a[tM][3] = __float_as_uint(As[mb + 8][kk + r + 4]);
            }
#pragma unroll
            for (int nT = 0; nT < 8; nT++) {
                b[nT][0] = __float_as_uint(Bs[kk + r    ][nT * 8 + qd]);
                b[nT][1] = __float_as_uint(Bs[kk + r + 4][nT * 8 + qd]);
            }
#pragma unroll
            for (int tM = 0; tM < 2; tM++)
#pragma unroll
                for (int nT = 0; nT < 8; nT++) {
                    asm volatile(
                        "mma.sync.aligned.m16n8k8.row.col.f32.tf32.tf32.f32 "
                        "{%0,%1,%2,%3}, {%4,%5,%6,%7}, {%8,%9}, {%0,%1,%2,%3};"
                        : "+f"(acc[tM][nT][0]), "+f"(acc[tM][nT][1]),
                          "+f"(acc[tM][nT][2]), "+f"(acc[tM][nT][3])
                        : "r"(a[tM][0]), "r"(a[tM][1]), "r"(a[tM][2]), "r"(a[tM][3]),
                          "r"(b[nT][0]), "r"(b[nT][1]));
                }
        }
        __syncthreads();
    }

#pragma unroll
    for (int tM = 0; tM < 2; tM++) {
        int row0 = t0 + mW + tM * 16 + qd;
#pragma unroll
        for (int nT = 0; nT < 8; nT++) {
            int col = nT * 8 + 2 * r;
            if (row0 < TD)
                *(float2*)&outp[row0 * 64 + col] = make_float2(acc[tM][nT][0], acc[tM][nT][1]);
            if (row0 + 8 < TD)
                *(float2*)&outp[(row0 + 8) * 64 + col] = make_float2(acc[tM][nT][2], acc[tM][nT][3]);
        }
    }
}

// ---------------- kernel 3: 72-tap causal FIR per channel ----------------
#define TT 1024

__global__ __launch_bounds__(256) void fir_kernel(const float* __restrict__ Wsyn,
                                                  const float* __restrict__ Tausyn,
                                                  const float* __restrict__ Dsyn) {
    __shared__ __align__(16) float xe[4 + TT + NTAPS + 4];
    __shared__ __align__(16) float xi[4 + TT + NTAPS + 4];
    __shared__ __align__(16) float ke[NTAPS + 4];
    __shared__ __align__(16) float ki[NTAPS + 4];
    int p  = blockIdx.y;          // channel 0..59
    int s  = p % 20;
    int c  = p;
    int t0 = blockIdx.x * TT;
    int tid = threadIdx.x;

    if (tid < NTAPS + 4) {
        float kv0 = 0.f, kv1 = 0.f;
        if (tid < NTAPS) {
            float itau0 = expf(-Tausyn[s * 2 + 0]);
            float itau1 = expf(-Tausyn[s * 2 + 1]);
            float d0 = expf(Dsyn[s * 2 + 0]);
            float d1 = expf(Dsyn[s * 2 + 1]);
            float w0 = Wsyn[s * 2 + 0], w1 = Wsyn[s * 2 + 1];
            float tt_ = fmaxf((float)tid - d0, 0.0f) * itau0;
            kv0 = tt_ * expf(-tt_) * w0;
            tt_ = fmaxf((float)tid - d1, 0.0f) * itau1;
            kv1 = tt_ * expf(-tt_) * w1;
        }
        ke[tid] = kv0; ki[tid] = kv1;
    }
    for (int idx = tid; idx < TT + NTAPS; idx += 256) {
        int g = t0 - NTAPS + idx;
        float ve = 0.f, vi = 0.f;
        if (g >= 0 && g < TD) {
            ve = g_inE[0][g * 64 + c] + g_inE[1][g * 64 + c]
               + g_inE[2][g * 64 + c] + g_inE[3][g * 64 + c];
            vi = g_inI[g * 64 + c];
        }
        xe[4 + idx] = ve;
        xi[4 + idx] = vi;
    }
    if (tid < 4) { xe[tid] = 0.f; xi[tid] = 0.f; }
    __syncthreads();

    float acc0 = 0.f, acc1 = 0.f, acc2 = 0.f, acc3 = 0.f;
    int pos = NTAPS + tid * 4;
    {
        float w[8];
        *(float4*)&w[4] = *(float4*)&xe[4 + pos];
#pragma unroll 6
        for (int tau = 0; tau <= NTAPS - 4; tau += 4) {
            *(float4*)&w[0] = *(float4*)&xe[pos - tau];
            float4 kk = *(float4*)&ke[tau];
            acc0 += kk.x * w[4]; acc1 += kk.x * w[5]; acc2 += kk.x * w[6]; acc3 += kk.x * w[7];
            acc0 += kk.y * w[3]; acc1 += kk.y * w[4]; acc2 += kk.y * w[5]; acc3 += kk.y * w[6];
            acc0 += kk.z * w[2]; acc1 += kk.z * w[3]; acc2 += kk.z * w[4]; acc3 += kk.z * w[5];
            acc0 += kk.w * w[1]; acc1 += kk.w * w[2]; acc2 += kk.w * w[3]; acc3 += kk.w * w[4];
            w[4] = w[0]; w[5] = w[1]; w[6] = w[2]; w[7] = w[3];
        }
    }
    {
        float w[8];
        *(float4*)&w[4] = *(float4*)&xi[4 + pos];
#pragma unroll 6
        for (int tau = 0; tau <= NTAPS - 4; tau += 4) {
            *(float4*)&w[0] = *(float4*)&xi[pos - tau];
            float4 kk = *(float4*)&ki[tau];
            acc0 += kk.x * w[4]; acc1 += kk.x * w[5]; acc2 += kk.x * w[6]; acc3 += kk.x * w[7];
            acc0 += kk.y * w[3]; acc1 += kk.y * w[4]; acc2 += kk.y * w[5]; acc3 += kk.y * w[6];
            acc0 += kk.z * w[2]; acc1 += kk.z * w[3]; acc2 += kk.z * w[4]; acc3 += kk.z * w[5];
            acc0 += kk.w * w[1]; acc1 += kk.w * w[2]; acc2 += kk.w * w[3]; acc3 += kk.w * w[4];
            w[4] = w[0]; w[5] = w[1]; w[6] = w[2]; w[7] = w[3];
        }
    }
    int t = t0 + tid * 4;
    if (t < TD)
        *(float4*)&g_syn[p][t] = make_float4(acc0, acc1, acc2, acc3);
}

// ---------------- kernel 4: subunit tree + output ----------------
__global__ void tree_kernel(const float* __restrict__ Wsub, const float* __restrict__ Vo,
                            float* __restrict__ out) {
    int t = blockIdx.x * blockDim.x + threadIdx.x;
    int var = blockIdx.y;
    if (t >= TD) return;
    float W[20];
#pragma unroll
    for (int s = 0; s < 20; s++) W[s] = Wsub[s];
    float vo = Vo[0];
    float sub[20];
#pragma unroll
    for (int s = 19; s >= 10; s--) sub[s] = tanhf(g_syn[var * 20 + s][t]);
    sub[9] = tanhf(g_syn[var * 20 + 9][t] + sub[19] * W[19]);
#pragma unroll
    for (int s = 8; s >= 0; s--)
        sub[s] = tanhf(g_syn[var * 20 + s][t]
                       + sub[2 * s + 1] * W[2 * s + 1]
                       + sub[2 * s + 2] * W[2 * s + 2]);
    out[var * TD + t] = sub[0] * W[0] + vo;
}

// ---------------- launch ----------------
extern "C" void kernel_launch(void* const* d_in, const int* in_sizes, int n_in,
                              void* d_out, int out_size) {
    const float* Se   = (const float*)d_in[0];
    const float* Si   = (const float*)d_in[1];
    const float* u    = (const float*)d_in[2];
    const float* v    = (const float*)d_in[3];
    const float* Wsyn = (const float*)d_in[4];
    const float* Tau  = (const float*)d_in[5];
    const float* Dlt  = (const float*)d_in[6];
    const float* Wsub = (const float*)d_in[7];
    const float* Vo   = (const float*)d_in[8];
    const float* Cl   = (const float*)d_in[10];
    float* out = (float*)d_out;

    prep_kernel<<<(KTOT + 3) / 4, 128>>>(u, v, Cl, out);
    dim3 gg((TD + BM - 1) / BM, NQ + 1);       // (157, 5)
    gemm_kernel<<<gg, 128>>>(Se, Si);
    dim3 gf((TD + TT - 1) / TT, 60);           // (20, 60)
    fir_kernel<<<gf, 256>>>(Wsyn, Tau, Dlt);
    dim3 gt((TD + 255) / 256, 3);
    tree_kernel<<<gt, 256>>>(Wsub, Vo, out);
}

// round 6
// speedup vs baseline: 1.9589x; 1.1795x over previous
#include <cuda_runtime.h>
#include <cuda_bf16.h>
#include <math.h>

#define SUB   20
#define ENO   2000
#define INO   500
#define TD    20000
#define KTOT  2500
#define NQ    4
#define NTAPS 72

// ---------------- device scratch ----------------
// B matrix, transposed + bf16, quarter-padded: [c][q][k_local], k_local 0..511 (500..511 zero)
__device__ __align__(16) __nv_bfloat16 g_CtT[64][NQ + 1][512];
__device__ float g_inE[NQ][TD * 64];
__device__ float g_inI[TD * 64];
__device__ float g_syn[60][TD];

__device__ __forceinline__ unsigned smem_u32(const void* p) {
    return (unsigned)__cvta_generic_to_shared(p);
}
__device__ __forceinline__ unsigned pack_bf2(float a, float b) {
    __nv_bfloat162 h = __floats2bfloat162_rn(a, b);
    return *(unsigned*)&h;
}

// ---------------- kernel 1: prep (warp per column n, s -> lane) ----------------
__global__ __launch_bounds__(128) void prep_kernel(const float* __restrict__ u,
                                                   const float* __restrict__ v,
                                                   const float* __restrict__ cl,
                                                   float* __restrict__ out) {
    // block 0 additionally zeroes the k-pad region of g_CtT (500..511 per quarter)
    if (blockIdx.x == 0) {
        for (int idx = threadIdx.x; idx < 64 * (NQ + 1) * 12; idx += 128) {
            int c = idx / ((NQ + 1) * 12);
            int rem = idx % ((NQ + 1) * 12);
            int q = rem / 12, kl = 500 + rem % 12;
            g_CtT[c][q][kl] = __float2bfloat16(0.0f);
        }
    }
    int warp = threadIdx.x >> 5, lane = threadIdx.x & 31;
    int n = blockIdx.x * 4 + warp;
    if (n >= KTOT) return;
    int s = lane;
    bool act = (s < SUB);

    float c = act ? cl[s * KTOT + n] : -1e30f;
    float m = c;
#pragma unroll
    for (int o = 16; o; o >>= 1) m = fmaxf(m, __shfl_xor_sync(0xffffffffu, m, o));
    float e = act ? expf(c - m) : 0.0f;
    float sum = e;
#pragma unroll
    for (int o = 16; o; o >>= 1) sum += __shfl_xor_sync(0xffffffffu, sum, o);
    float theta = e / sum;

    float uu = act ? u[s * KTOT + n] : 0.5f;
    float vv = act ? v[s * KTOT + n] : 0.5f;
    float rz = act ? (logf(theta) - logf(-logf(uu))) : -1e30f;

    float best = rz; int bidx = s;
#pragma unroll
    for (int o = 16; o; o >>= 1) {
        float ob = __shfl_xor_sync(0xffffffffu, best, o);
        int   oi = __shfl_xor_sync(0xffffffffu, bidx, o);
        if (ob > best || (ob == best && oi < bidx)) { best = ob; bidx = oi; }
    }
    int k = bidx;
    float vk  = __shfl_sync(0xffffffffu, vv, k);
    float lvk = logf(vk);

    if (act) {
        float hard = (s == k) ? 1.0f : 0.0f;
        float soft = 1.0f / (1.0f + expf(-2.0f * rz)) + 1e-9f;
        float zb   = (s == k) ? -logf(-logf(vv))
                              : -logf((-logf(vv)) / theta - lvk);
        float szb  = 1.0f / (1.0f + expf(-2.0f * zb)) + 1e-9f;
        out[ 60000 + s * KTOT + n] = theta;
        out[110000 + s * KTOT + n] = hard;
        out[160000 + s * KTOT + n] = soft;
        out[210000 + s * KTOT + n] = szb;
        int q = (n < 2000) ? (n / 500) : NQ;
        int kl = (n < 2000) ? (n % 500) : (n - 2000);
        g_CtT[s     ][q][kl] = __float2bfloat16(hard);
        g_CtT[20 + s][q][kl] = __float2bfloat16_rn(soft);
        g_CtT[40 + s][q][kl] = __float2bfloat16_rn(szb);
        if (s < 4) g_CtT[60 + s][q][kl] = __float2bfloat16(0.0f);  // pad cols
    }
}

// ---------------- kernel 2: bf16 tensor-core GEMM ----------------
#define BM 128
#define BKC 32   // bf16 k per chunk

__global__ __launch_bounds__(128) void gemm_kernel(const float* __restrict__ Se,
                                                   const float* __restrict__ Si) {
    __shared__ __align__(16) __nv_bfloat16 As[BM][40];   // pad 40 -> conflict-free LDSM
    __shared__ __align__(16) __nv_bfloat16 Bt[64][40];   // [n][k]
    int q  = blockIdx.y;
    int t0 = blockIdx.x * BM;
    const float* A; int lda, k0;  float* outp;
    if (q < NQ) { A = Se; lda = ENO; k0 = q * 500; outp = g_inE[q]; }
    else        { A = Si; lda = INO; k0 = 0;       outp = g_inI;    }

    int tid = threadIdx.x, warp = tid >> 5, lane = tid & 31;
    int qd = lane >> 2, r = lane & 3;
    int mW = warp * 32;

    float acc[2][8][4];
#pragma unroll
    for (int a = 0; a < 2; a++)
#pragma unroll
        for (int b = 0; b < 8; b++)
#pragma unroll
            for (int cc = 0; cc < 4; cc++) acc[a][b][cc] = 0.0f;

    int t = t0 + tid;
    bool trow = (t < TD);
    const float* arow = trow ? &A[(size_t)t * lda + k0] : A;

    // ldmatrix source addresses
    int a_row  = mW + (lane & 15);
    int a_koff = (lane >> 4) * 8;
    unsigned a_addr0 = smem_u32(&As[a_row][a_koff]);
    unsigned a_addr1 = a_addr0 + 16 * 40 * 2;
    int g2 = lane >> 3;                        // 0..3
    int b_row  = (g2 >> 1) * 8 + (lane & 7);   // row within n-tile pair
    int b_koff = (g2 & 1) * 8;
    unsigned b_addr = smem_u32(&Bt[b_row][b_koff]);

    for (int kc = 0; kc < 16; kc++) {
        // stage A: this thread's row, 32 k (fp32 -> bf16)
#pragma unroll
        for (int c8 = 0; c8 < 4; c8++) {
            int k8 = kc * 32 + c8 * 8;
            float4 f0 = make_float4(0.f, 0.f, 0.f, 0.f);
            float4 f1 = make_float4(0.f, 0.f, 0.f, 0.f);
            if (trow && k8 < 500)     f0 = *(const float4*)&arow[k8];
            if (trow && k8 + 4 < 500) f1 = *(const float4*)&arow[k8 + 4];
            uint4 uu;
            uu.x = pack_bf2(f0.x, f0.y); uu.y = pack_bf2(f0.z, f0.w);
            uu.z = pack_bf2(f1.x, f1.y); uu.w = pack_bf2(f1.z, f1.w);
            *(uint4*)&As[tid][c8 * 8] = uu;
        }
        // stage B: 64 n-rows x 32 k bf16 (already packed, padded)
#pragma unroll
        for (int rr = 0; rr < 2; rr++) {
            int fi = tid + 128 * rr;
            int row = fi >> 2, uidx = fi & 3;
            *(uint4*)&Bt[row][uidx * 8] =
                *(const uint4*)&g_CtT[row][q][kc * 32 + uidx * 8];
        }
        __syncthreads();

#pragma unroll
        for (int kk = 0; kk < 32; kk += 16) {
            unsigned a0[4], a1[4], b[8][2];
            asm volatile("ldmatrix.sync.aligned.m8n8.x4.shared.b16 {%0,%1,%2,%3}, [%4];"
                         : "=r"(a0[0]), "=r"(a0[1]), "=r"(a0[2]), "=r"(a0[3])
                         : "r"(a_addr0 + kk * 2));
            asm volatile("ldmatrix.sync.aligned.m8n8.x4.shared.b16 {%0,%1,%2,%3}, [%4];"
                         : "=r"(a1[0]), "=r"(a1[1]), "=r"(a1[2]), "=r"(a1[3])
                         : "r"(a_addr1 + kk * 2));
#pragma unroll
            for (int p = 0; p < 4; p++) {
                asm volatile("ldmatrix.sync.aligned.m8n8.x4.shared.b16 {%0,%1,%2,%3}, [%4];"
                             : "=r"(b[2 * p][0]), "=r"(b[2 * p][1]),
                               "=r"(b[2 * p + 1][0]), "=r"(b[2 * p + 1][1])
                             : "r"(b_addr + p * (16 * 40 * 2) + kk * 2));
            }
#pragma unroll
            for (int nT = 0; nT < 8; nT++) {
                asm volatile(
                    "mma.sync.aligned.m16n8k16.row.col.f32.bf16.bf16.f32 "
                    "{%0,%1,%2,%3}, {%4,%5,%6,%7}, {%8,%9}, {%0,%1,%2,%3};"
                    : "+f"(acc[0][nT][0]), "+f"(acc[0][nT][1]),
                      "+f"(acc[0][nT][2]), "+f"(acc[0][nT][3])
                    : "r"(a0[0]), "r"(a0[1]), "r"(a0[2]), "r"(a0[3]),
                      "r"(b[nT][0]), "r"(b[nT][1]));
                asm volatile(
                    "mma.sync.aligned.m16n8k16.row.col.f32.bf16.bf16.f32 "
                    "{%0,%1,%2,%3}, {%4,%5,%6,%7}, {%8,%9}, {%0,%1,%2,%3};"
                    : "+f"(acc[1][nT][0]), "+f"(acc[1][nT][1]),
                      "+f"(acc[1][nT][2]), "+f"(acc[1][nT][3])
                    : "r"(a1[0]), "r"(a1[1]), "r"(a1[2]), "r"(a1[3]),
                      "r"(b[nT][0]), "r"(b[nT][1]));
            }
        }
        __syncthreads();
    }

#pragma unroll
    for (int tM = 0; tM < 2; tM++) {
        int row0 = t0 + mW + tM * 16 + qd;
#pragma unroll
        for (int nT = 0; nT < 8; nT++) {
            int col = nT * 8 + 2 * r;
            if (row0 < TD)
                *(float2*)&outp[row0 * 64 + col] = make_float2(acc[tM][nT][0], acc[tM][nT][1]);
            if (row0 + 8 < TD)
                *(float2*)&outp[(row0 + 8) * 64 + col] = make_float2(acc[tM][nT][2], acc[tM][nT][3]);
        }
    }
}

// ---------------- kernel 3: 72-tap causal FIR per channel ----------------
#define TT 1024

__global__ __launch_bounds__(256) void fir_kernel(const float* __restrict__ Wsyn,
                                                  const float* __restrict__ Tausyn,
                                                  const float* __restrict__ Dsyn) {
    __shared__ __align__(16) float xe[4 + TT + NTAPS + 4];
    __shared__ __align__(16) float xi[4 + TT + NTAPS + 4];
    __shared__ __align__(16) float ke[NTAPS + 4];
    __shared__ __align__(16) float ki[NTAPS + 4];
    int p  = blockIdx.y;
    int s  = p % 20;
    int c  = p;
    int t0 = blockIdx.x * TT;
    int tid = threadIdx.x;

    if (tid < NTAPS + 4) {
        float kv0 = 0.f, kv1 = 0.f;
        if (tid < NTAPS) {
            float itau0 = expf(-Tausyn[s * 2 + 0]);
            float itau1 = expf(-Tausyn[s * 2 + 1]);
            float d0 = expf(Dsyn[s * 2 + 0]);
            float d1 = expf(Dsyn[s * 2 + 1]);
            float w0 = Wsyn[s * 2 + 0], w1 = Wsyn[s * 2 + 1];
            float tt_ = fmaxf((float)tid - d0, 0.0f) * itau0;
            kv0 = tt_ * expf(-tt_) * w0;
            tt_ = fmaxf((float)tid - d1, 0.0f) * itau1;
            kv1 = tt_ * expf(-tt_) * w1;
        }
        ke[tid] = kv0; ki[tid] = kv1;
    }
    for (int idx = tid; idx < TT + NTAPS; idx += 256) {
        int g = t0 - NTAPS + idx;
        float ve = 0.f, vi = 0.f;
        if (g >= 0 && g < TD) {
            ve = g_inE[0][g * 64 + c] + g_inE[1][g * 64 + c]
               + g_inE[2][g * 64 + c] + g_inE[3][g * 64 + c];
            vi = g_inI[g * 64 + c];
        }
        xe[4 + idx] = ve;
        xi[4 + idx] = vi;
    }
    if (tid < 4) { xe[tid] = 0.f; xi[tid] = 0.f; }
    __syncthreads();

    float acc0 = 0.f, acc1 = 0.f, acc2 = 0.f, acc3 = 0.f;
    int pos = NTAPS + tid * 4;
    {
        float w[8];
        *(float4*)&w[4] = *(float4*)&xe[4 + pos];
#pragma unroll 6
        for (int tau = 0; tau <= NTAPS - 4; tau += 4) {
            *(float4*)&w[0] = *(float4*)&xe[pos - tau];
            float4 kk = *(float4*)&ke[tau];
            acc0 += kk.x * w[4]; acc1 += kk.x * w[5]; acc2 += kk.x * w[6]; acc3 += kk.x * w[7];
            acc0 += kk.y * w[3]; acc1 += kk.y * w[4]; acc2 += kk.y * w[5]; acc3 += kk.y * w[6];
            acc0 += kk.z * w[2]; acc1 += kk.z * w[3]; acc2 += kk.z * w[4]; acc3 += kk.z * w[5];
            acc0 += kk.w * w[1]; acc1 += kk.w * w[2]; acc2 += kk.w * w[3]; acc3 += kk.w * w[4];
            w[4] = w[0]; w[5] = w[1]; w[6] = w[2]; w[7] = w[3];
        }
    }
    {
        float w[8];
        *(float4*)&w[4] = *(float4*)&xi[4 + pos];
#pragma unroll 6
        for (int tau = 0; tau <= NTAPS - 4; tau += 4) {
            *(float4*)&w[0] = *(float4*)&xi[pos - tau];
            float4 kk = *(float4*)&ki[tau];
            acc0 += kk.x * w[4]; acc1 += kk.x * w[5]; acc2 += kk.x * w[6]; acc3 += kk.x * w[7];
            acc0 += kk.y * w[3]; acc1 += kk.y * w[4]; acc2 += kk.y * w[5]; acc3 += kk.y * w[6];
            acc0 += kk.z * w[2]; acc1 += kk.z * w[3]; acc2 += kk.z * w[4]; acc3 += kk.z * w[5];
            acc0 += kk.w * w[1]; acc1 += kk.w * w[2]; acc2 += kk.w * w[3]; acc3 += kk.w * w[4];
            w[4] = w[0]; w[5] = w[1]; w[6] = w[2]; w[7] = w[3];
        }
    }
    int t = t0 + tid * 4;
    if (t < TD)
        *(float4*)&g_syn[p][t] = make_float4(acc0, acc1, acc2, acc3);
}

// ---------------- kernel 4: subunit tree + output ----------------
__global__ void tree_kernel(const float* __restrict__ Wsub, const float* __restrict__ Vo,
                            float* __restrict__ out) {
    int t = blockIdx.x * blockDim.x + threadIdx.x;
    int var = blockIdx.y;
    if (t >= TD) return;
    float W[20];
#pragma unroll
    for (int s = 0; s < 20; s++) W[s] = Wsub[s];
    float vo = Vo[0];
    float sub[20];
#pragma unroll
    for (int s = 19; s >= 10; s--) sub[s] = tanhf(g_syn[var * 20 + s][t]);
    sub[9] = tanhf(g_syn[var * 20 + 9][t] + sub[19] * W[19]);
#pragma unroll
    for (int s = 8; s >= 0; s--)
        sub[s] = tanhf(g_syn[var * 20 + s][t]
                       + sub[2 * s + 1] * W[2 * s + 1]
                       + sub[2 * s + 2] * W[2 * s + 2]);
    out[var * TD + t] = sub[0] * W[0] + vo;
}

// ---------------- launch ----------------
extern "C" void kernel_launch(void* const* d_in, const int* in_sizes, int n_in,
                              void* d_out, int out_size) {
    const float* Se   = (const float*)d_in[0];
    const float* Si   = (const float*)d_in[1];
    const float* u    = (const float*)d_in[2];
    const float* v    = (const float*)d_in[3];
    const float* Wsyn = (const float*)d_in[4];
    const float* Tau  = (const float*)d_in[5];
    const float* Dlt  = (const float*)d_in[6];
    const float* Wsub = (const float*)d_in[7];
    const float* Vo   = (const float*)d_in[8];
    const float* Cl   = (const float*)d_in[10];
    float* out = (float*)d_out;

    prep_kernel<<<(KTOT + 3) / 4, 128>>>(u, v, Cl, out);
    dim3 gg((TD + BM - 1) / BM, NQ + 1);       // (157, 5)
    gemm_kernel<<<gg, 128>>>(Se, Si);
    dim3 gf((TD + TT - 1) / TT, 60);           // (20, 60)
    fir_kernel<<<gf, 256>>>(Wsyn, Tau, Dlt);
    dim3 gt((TD + 255) / 256, 3);
    tree_kernel<<<gt, 256>>>(Wsub, Vo, out);
}